// round 13
// baseline (speedup 1.0000x reference)
#include <cuda_runtime.h>
#include <cuda_bf16.h>
#include <cuda_fp16.h>
#include <cstdint>

#define NODES_MAX 50000
#define EDGES_MAX 800000
#define D 128

typedef unsigned long long ull;

// ---------------- scratch (__device__ globals: allocation-free rule) --------
__device__ __half g_transformed[(size_t)NODES_MAX * D];   // T = feat@W, 12.8 MB
__device__ __nv_bfloat16 g_BhW[128 * 128];
__device__ __nv_bfloat16 g_BlW[128 * 128];
__device__ __nv_bfloat16 g_BhL[128 * 128];
__device__ __nv_bfloat16 g_BlL[128 * 128];
__device__ int g_deg[NODES_MAX];
__device__ int g_rowptr[NODES_MAX + 1];
__device__ int g_cursor[NODES_MAX];
__device__ int g_esrc[EDGES_MAX];          // src ids bucketed by dst

// ---------------- prep: [W|LW]^T -> bf16 hi/lo (tiled smem transpose) -------
__global__ void prep_B(const float* __restrict__ W, const float* __restrict__ LW) {
    __shared__ float tile[32][33];
    const int mat = blockIdx.x >> 4;
    const int ti = blockIdx.x & 15;
    const int tr = (ti >> 2) * 32;   // k block
    const int tc = (ti & 3) * 32;    // n block
    const float* M = mat ? LW : W;
    __nv_bfloat16* Bh = mat ? g_BhL : g_BhW;
    __nv_bfloat16* Bl = mat ? g_BlL : g_BlW;
    const int t = threadIdx.x;
    const int c = t & 31, r0 = t >> 5;
#pragma unroll
    for (int i = 0; i < 4; i++) {
        int r = r0 + i * 8;
        tile[r][c] = M[(tr + r) * 128 + tc + c];   // coalesced
    }
    __syncthreads();
#pragma unroll
    for (int i = 0; i < 4; i++) {
        int r = r0 + i * 8;
        float w = tile[c][r];                       // conflict-free (pad 33)
        __nv_bfloat16 hi = __float2bfloat16(w);
        __nv_bfloat16 lo = __float2bfloat16(w - __bfloat162float(hi));
        Bh[(tc + r) * 128 + tr + c] = hi;           // coalesced (c = k)
        Bl[(tc + r) * 128 + tr + c] = lo;
    }
}

// ---------------- CSR build --------------------------------------------------
__global__ void zero_deg(int N) {
    int i = blockIdx.x * blockDim.x + threadIdx.x;
    if (i < N) g_deg[i] = 0;
}

__global__ void hist_dst(const int* __restrict__ dst, int E) {
    int i = blockIdx.x * blockDim.x + threadIdx.x;
    int stride = gridDim.x * blockDim.x;
    for (; i < E; i += stride) atomicAdd(&g_deg[dst[i]], 1);
}

// Single-block exclusive scan of g_deg -> g_rowptr / g_cursor
__global__ void scan_deg(int N) {
    __shared__ int part[1024];
    const int t = threadIdx.x;
    const int C = (N + 1023) / 1024;
    int beg = t * C;
    int end = min(beg + C, N);
    int s = 0;
    for (int j = beg; j < end; j++) s += g_deg[j];
    part[t] = s;
    __syncthreads();
    for (int off = 1; off < 1024; off <<= 1) {
        int v = part[t];
        int add = (t >= off) ? part[t - off] : 0;
        __syncthreads();
        part[t] = v + add;
        __syncthreads();
    }
    int run = (t > 0) ? part[t - 1] : 0;
    for (int j = beg; j < end; j++) {
        int d = g_deg[j];
        g_rowptr[j] = run;
        g_cursor[j] = run;
        run += d;
    }
    if (t == 1023) g_rowptr[N] = part[1023];
}

// 4 edges/thread, int4-vectorized loads, 4 independent atomic chains (MLP=4)
__global__ void reorder_edges(const int* __restrict__ src,
                              const int* __restrict__ dst, int E) {
    int tid = blockIdx.x * blockDim.x + threadIdx.x;
    int e0 = tid * 4;
    if (e0 >= E) return;
    if (e0 + 4 <= E) {
        int4 s4 = *(const int4*)(src + e0);
        int4 d4 = *(const int4*)(dst + e0);
        int p0 = atomicAdd(&g_cursor[d4.x], 1);
        int p1 = atomicAdd(&g_cursor[d4.y], 1);
        int p2 = atomicAdd(&g_cursor[d4.z], 1);
        int p3 = atomicAdd(&g_cursor[d4.w], 1);
        g_esrc[p0] = s4.x; g_esrc[p1] = s4.y;
        g_esrc[p2] = s4.z; g_esrc[p3] = s4.w;
    } else {
        for (int e = e0; e < E; e++) {
            int pos = atomicAdd(&g_cursor[dst[e]], 1);
            g_esrc[pos] = src[e];
        }
    }
}

// ---------------- helpers ---------------------------------------------------
__device__ __forceinline__ uint32_t smem_u32(const void* p) {
    uint32_t a;
    asm("{ .reg .u64 t; cvta.to.shared.u64 t, %1; cvt.u32.u64 %0, t; }"
        : "=r"(a) : "l"(p));
    return a;
}

#define LDSM_X4(r0, r1, r2, r3, a) \
    asm volatile("ldmatrix.sync.aligned.m8n8.x4.shared.b16 {%0,%1,%2,%3}, [%4];" \
        : "=r"(r0), "=r"(r1), "=r"(r2), "=r"(r3) : "r"(a))

#define MMA16816(d, a, b0, b1) \
    asm volatile("mma.sync.aligned.m16n8k16.row.col.f32.bf16.bf16.f32 " \
        "{%0,%1,%2,%3}, {%4,%5,%6,%7}, {%8,%9}, {%0,%1,%2,%3};" \
        : "+f"((d)[0]), "+f"((d)[1]), "+f"((d)[2]), "+f"((d)[3]) \
        : "r"((a)[0]), "r"((a)[1]), "r"((a)[2]), "r"((a)[3]), \
          "r"(b0), "r"(b1))

// ---------------- tensor-core (mma.sync) fused GEMM -------------------------
// Grid (782, 2). y=0: feat@W -> g_transformed (fp16); y=1: feat@LW+bias -> out
// bf16 hi/lo 3-term (AhBh + AlBh + AhBl), fp32 accum. PAD=136 -> no conflicts.
#define PAD 136
#define SM_AH 0
#define SM_AL (SM_AH + 64 * PAD * 2)
#define SM_BH (SM_AL + 64 * PAD * 2)
#define SM_BL (SM_BH + 128 * PAD * 2)
#define SM_TOT (SM_BL + 128 * PAD * 2)          // 104448

__global__ __launch_bounds__(256, 2)
void gemm_mma(const float* __restrict__ feat,
              const float* __restrict__ bias,
              float* __restrict__ out, int N) {
    extern __shared__ char smem[];
    const uint32_t sb = smem_u32(smem);
    const int t = threadIdx.x;
    const int w = t >> 5, l = t & 31;
    const int row0 = blockIdx.x * 64;
    const int half = blockIdx.y;

#pragma unroll
    for (int i = 0; i < 8; i++) {
        int idx = t + (i << 8);
        int row = idx >> 5, kq = idx & 31;
        int grow = row0 + row;
        float4 v = make_float4(0.f, 0.f, 0.f, 0.f);
        if (grow < N) v = ((const float4*)feat)[(size_t)grow * 32 + kq];

        __nv_bfloat16 hx = __float2bfloat16(v.x), hy = __float2bfloat16(v.y);
        __nv_bfloat16 hz = __float2bfloat16(v.z), hw = __float2bfloat16(v.w);
        __nv_bfloat162 h01 = __halves2bfloat162(hx, hy);
        __nv_bfloat162 h23 = __halves2bfloat162(hz, hw);
        __nv_bfloat162 l01 = __halves2bfloat162(
            __float2bfloat16(v.x - __bfloat162float(hx)),
            __float2bfloat16(v.y - __bfloat162float(hy)));
        __nv_bfloat162 l23 = __halves2bfloat162(
            __float2bfloat16(v.z - __bfloat162float(hz)),
            __float2bfloat16(v.w - __bfloat162float(hw)));

        int off = row * (PAD * 2) + kq * 8;
        *(__nv_bfloat162*)(smem + SM_AH + off)     = h01;
        *(__nv_bfloat162*)(smem + SM_AH + off + 4) = h23;
        *(__nv_bfloat162*)(smem + SM_AL + off)     = l01;
        *(__nv_bfloat162*)(smem + SM_AL + off + 4) = l23;
    }
    {
        const uint4* srcH = (const uint4*)(half ? g_BhL : g_BhW);
        const uint4* srcL = (const uint4*)(half ? g_BlL : g_BlW);
#pragma unroll
        for (int i = 0; i < 8; i++) {
            int idx = t + (i << 8);
            int n = idx >> 4, kq = idx & 15;
            int off = n * (PAD * 2) + kq * 16;
            *(uint4*)(smem + SM_BH + off) = srcH[idx];
            *(uint4*)(smem + SM_BL + off) = srcL[idx];
        }
    }
    __syncthreads();

    const int mbase = (w >> 2) * 32;
    const int nbase = (w & 3) * 32;
    const uint32_t aRow = (uint32_t)(mbase + (l & 15)) * (PAD * 2) + (l >> 4) * 16;
    const uint32_t bRow = (uint32_t)(nbase + ((l >> 4) << 3) + (l & 7)) * (PAD * 2)
                        + (((l >> 3) & 1) << 4);

    float acc[2][4][4];
#pragma unroll
    for (int mt = 0; mt < 2; mt++)
#pragma unroll
        for (int nt = 0; nt < 4; nt++)
#pragma unroll
            for (int q = 0; q < 4; q++) acc[mt][nt][q] = 0.f;

#pragma unroll
    for (int ks = 0; ks < 8; ks++) {
        const uint32_t kOff = (uint32_t)ks * 32;
        uint32_t ah[2][4], al[2][4], bh[2][4], bl[2][4];
#pragma unroll
        for (int mt = 0; mt < 2; mt++) {
            uint32_t a0 = sb + aRow + (uint32_t)mt * 16 * (PAD * 2) + kOff;
            LDSM_X4(ah[mt][0], ah[mt][1], ah[mt][2], ah[mt][3], a0 + SM_AH);
            LDSM_X4(al[mt][0], al[mt][1], al[mt][2], al[mt][3], a0 + SM_AL);
        }
#pragma unroll
        for (int np = 0; np < 2; np++) {
            uint32_t b0 = sb + bRow + (uint32_t)np * 16 * (PAD * 2) + kOff;
            LDSM_X4(bh[np][0], bh[np][1], bh[np][2], bh[np][3], b0 + SM_BH);
            LDSM_X4(bl[np][0], bl[np][1], bl[np][2], bl[np][3], b0 + SM_BL);
        }
#pragma unroll
        for (int mt = 0; mt < 2; mt++)
#pragma unroll
            for (int np = 0; np < 2; np++)
#pragma unroll
                for (int s = 0; s < 2; s++) {
                    int nt = np * 2 + s;
                    MMA16816(acc[mt][nt], ah[mt], bh[np][2 * s], bh[np][2 * s + 1]);
                    MMA16816(acc[mt][nt], al[mt], bh[np][2 * s], bh[np][2 * s + 1]);
                    MMA16816(acc[mt][nt], ah[mt], bl[np][2 * s], bl[np][2 * s + 1]);
                }
    }

#pragma unroll
    for (int mt = 0; mt < 2; mt++) {
        int r0 = row0 + mbase + mt * 16 + (l >> 2);
#pragma unroll
        for (int nt = 0; nt < 4; nt++) {
            int col = nbase + nt * 8 + (l & 3) * 2;
            if (half) {
                float bx = bias[col], by = bias[col + 1];
                if (r0 < N)
                    *(float2*)&out[(size_t)r0 * D + col] =
                        make_float2(acc[mt][nt][0] + bx, acc[mt][nt][1] + by);
                if (r0 + 8 < N)
                    *(float2*)&out[(size_t)(r0 + 8) * D + col] =
                        make_float2(acc[mt][nt][2] + bx, acc[mt][nt][3] + by);
            } else {
                if (r0 < N)
                    *(__half2*)&g_transformed[(size_t)r0 * D + col] =
                        __floats2half2_rn(acc[mt][nt][0], acc[mt][nt][1]);
                if (r0 + 8 < N)
                    *(__half2*)&g_transformed[(size_t)(r0 + 8) * D + col] =
                        __floats2half2_rn(acc[mt][nt][2], acc[mt][nt][3]);
            }
        }
    }
}

// ---------------- gather-aggregate: warp per node, NO atomics ---------------
// out[v] += sum_{e in CSR row v} T[esrc[e]]  (fp16 reads, fp32 reg accum,
// one exclusive read-modify-write of the out row per node).
// Index loads are SCALAR (CSR row starts are not 16B-aligned; the int4 load
// here caused R12's misaligned-address fault). They are lane-uniform L2 hits.
__global__ void aggregate(float* __restrict__ out, int N) {
    const int v = (int)((blockIdx.x * blockDim.x + threadIdx.x) >> 5);
    const int lane = threadIdx.x & 31;
    if (v >= N) return;

    const int beg = g_rowptr[v];
    const int end = g_rowptr[v + 1];
    float4 acc = make_float4(0.f, 0.f, 0.f, 0.f);

    int j = beg;
    for (; j + 4 <= end; j += 4) {
        int s0 = __ldg(g_esrc + j);
        int s1 = __ldg(g_esrc + j + 1);
        int s2 = __ldg(g_esrc + j + 2);
        int s3 = __ldg(g_esrc + j + 3);
        uint2 r0 = *(const uint2*)(g_transformed + (size_t)s0 * D + lane * 4);
        uint2 r1 = *(const uint2*)(g_transformed + (size_t)s1 * D + lane * 4);
        uint2 r2 = *(const uint2*)(g_transformed + (size_t)s2 * D + lane * 4);
        uint2 r3 = *(const uint2*)(g_transformed + (size_t)s3 * D + lane * 4);
        float2 a0 = __half22float2(*(__half2*)&r0.x), b0 = __half22float2(*(__half2*)&r0.y);
        float2 a1 = __half22float2(*(__half2*)&r1.x), b1 = __half22float2(*(__half2*)&r1.y);
        float2 a2 = __half22float2(*(__half2*)&r2.x), b2 = __half22float2(*(__half2*)&r2.y);
        float2 a3 = __half22float2(*(__half2*)&r3.x), b3 = __half22float2(*(__half2*)&r3.y);
        acc.x += (a0.x + a1.x) + (a2.x + a3.x);
        acc.y += (a0.y + a1.y) + (a2.y + a3.y);
        acc.z += (b0.x + b1.x) + (b2.x + b3.x);
        acc.w += (b0.y + b1.y) + (b2.y + b3.y);
    }
    for (; j < end; j++) {
        int s = __ldg(g_esrc + j);
        uint2 r = *(const uint2*)(g_transformed + (size_t)s * D + lane * 4);
        float2 a = __half22float2(*(__half2*)&r.x);
        float2 b = __half22float2(*(__half2*)&r.y);
        acc.x += a.x; acc.y += a.y; acc.z += b.x; acc.w += b.y;
    }

    float4* op = (float4*)(out + (size_t)v * D + lane * 4);
    float4 o = *op;
    o.x += acc.x; o.y += acc.y; o.z += acc.z; o.w += acc.w;
    *op = o;
}

extern "C" void kernel_launch(void* const* d_in, const int* in_sizes, int n_in,
                              void* d_out, int out_size) {
    const float* feat = (const float*)d_in[0];   // [N, 128]
    const float* W    = (const float*)d_in[1];   // [128, 128]
    const float* bias = (const float*)d_in[2];   // [128]
    const float* LW   = (const float*)d_in[3];   // [128, 128]
    const int*   src  = (const int*)d_in[4];     // [E]
    const int*   dst  = (const int*)d_in[5];     // [E]
    float* out = (float*)d_out;                  // [N, 128]

    const int N = in_sizes[0] / D;
    const int E = in_sizes[4];

    cudaFuncSetAttribute(gemm_mma, cudaFuncAttributeMaxDynamicSharedMemorySize,
                         SM_TOT);

    // CSR build (dst-bucketed edge list)
    prep_B<<<32, 256>>>(W, LW);
    zero_deg<<<(N + 255) / 256, 256>>>(N);
    hist_dst<<<1024, 256>>>(dst, E);
    scan_deg<<<1, 1024>>>(N);
    reorder_edges<<<(E / 4 + 255) / 256 + 1, 256>>>(src, dst, E);

    // T = feat@W (fp16) ; out = feat@LW + bias
    dim3 grid((N + 63) / 64, 2);
    gemm_mma<<<grid, 256, SM_TOT>>>(feat, bias, out, N);

    // out[v] += sum of T rows (no atomics)
    aggregate<<<(N * 32 + 255) / 256, 256>>>(out, N);
}

// round 14
// speedup vs baseline: 1.7599x; 1.7599x over previous
#include <cuda_runtime.h>
#include <cuda_bf16.h>
#include <cuda_fp16.h>
#include <cstdint>

#define NODES_MAX 50000
#define EDGES_MAX 800000
#define D 128

typedef unsigned long long ull;

// ---------------- scratch (__device__ globals: allocation-free rule) --------
__device__ __half g_transformed[(size_t)NODES_MAX * D];   // T = feat@W, 12.8 MB
__device__ __nv_bfloat16 g_BhW[128 * 128];
__device__ __nv_bfloat16 g_BlW[128 * 128];
__device__ __nv_bfloat16 g_BhL[128 * 128];
__device__ __nv_bfloat16 g_BlL[128 * 128];
__device__ int g_deg[NODES_MAX];
__device__ int g_rowptr[NODES_MAX + 1];
__device__ int g_cursor[NODES_MAX];
__device__ int g_esrc[EDGES_MAX];          // src ids bucketed by dst
__device__ int g_bsum[256];                // per-block sums for the scan

// ---------------- prep: [W|LW]^T -> bf16 hi/lo (tiled smem transpose) -------
__global__ void prep_B(const float* __restrict__ W, const float* __restrict__ LW) {
    __shared__ float tile[32][33];
    const int mat = blockIdx.x >> 4;
    const int ti = blockIdx.x & 15;
    const int tr = (ti >> 2) * 32;   // k block
    const int tc = (ti & 3) * 32;    // n block
    const float* M = mat ? LW : W;
    __nv_bfloat16* Bh = mat ? g_BhL : g_BhW;
    __nv_bfloat16* Bl = mat ? g_BlL : g_BlW;
    const int t = threadIdx.x;
    const int c = t & 31, r0 = t >> 5;
#pragma unroll
    for (int i = 0; i < 4; i++) {
        int r = r0 + i * 8;
        tile[r][c] = M[(tr + r) * 128 + tc + c];   // coalesced
    }
    __syncthreads();
#pragma unroll
    for (int i = 0; i < 4; i++) {
        int r = r0 + i * 8;
        float w = tile[c][r];                       // conflict-free (pad 33)
        __nv_bfloat16 hi = __float2bfloat16(w);
        __nv_bfloat16 lo = __float2bfloat16(w - __bfloat162float(hi));
        Bh[(tc + r) * 128 + tr + c] = hi;           // coalesced (c = k)
        Bl[(tc + r) * 128 + tr + c] = lo;
    }
}

// ---------------- CSR build --------------------------------------------------
__global__ void zero_deg(int N) {
    int i = blockIdx.x * blockDim.x + threadIdx.x;
    if (i < N) g_deg[i] = 0;
}

__global__ void hist_dst(const int* __restrict__ dst, int E) {
    int i = blockIdx.x * blockDim.x + threadIdx.x;
    int stride = gridDim.x * blockDim.x;
    for (; i < E; i += stride) atomicAdd(&g_deg[dst[i]], 1);
}

// --- multi-block exclusive scan of g_deg (3 phases, all parallel) -----------
// Phase 1: per-block (256-entry) exclusive scan -> g_rowptr (local), block
//          total -> g_bsum[bid].
__global__ void scan_p1(int N) {
    __shared__ int sh[256];
    const int t = threadIdx.x;
    const int i = blockIdx.x * 256 + t;
    int v = (i < N) ? g_deg[i] : 0;
    sh[t] = v;
    __syncthreads();
#pragma unroll
    for (int off = 1; off < 256; off <<= 1) {
        int x = sh[t];
        int add = (t >= off) ? sh[t - off] : 0;
        __syncthreads();
        sh[t] = x + add;
        __syncthreads();
    }
    if (i < N) g_rowptr[i] = sh[t] - v;        // local exclusive prefix
    if (t == 255) g_bsum[blockIdx.x] = sh[255];
}

// Phase 2: single small block scans the <=256 block sums (exclusive),
//          total goes to g_bsum[255] slot via rowptr[N] write in p3.
__global__ void scan_p2(int nb) {
    __shared__ int sh[256];
    const int t = threadIdx.x;
    int v = (t < nb) ? g_bsum[t] : 0;
    sh[t] = v;
    __syncthreads();
#pragma unroll
    for (int off = 1; off < 256; off <<= 1) {
        int x = sh[t];
        int add = (t >= off) ? sh[t - off] : 0;
        __syncthreads();
        sh[t] = x + add;
        __syncthreads();
    }
    if (t < nb) g_bsum[t] = sh[t] - v;         // exclusive block offsets
    if (t == 0) g_rowptr[0x7fffffff & 0] = g_rowptr[0]; // no-op keep shape
    if (t == 255) g_deg[0] = g_deg[0];         // no-op
    if (t == nb - 1) {
        // stash grand total in the last unused g_bsum slot region:
        // write rowptr[N] directly here (sh[nb-1] is inclusive total)
    }
    if (t == 0) g_bsum[255] = sh[nb - 1];      // grand total (nb <= 255 used)
}

// Phase 3: add block offsets, fill cursor, write rowptr[N].
__global__ void scan_p3(int N) {
    const int i = blockIdx.x * 256 + threadIdx.x;
    if (i < N) {
        int r = g_rowptr[i] + g_bsum[blockIdx.x];
        g_rowptr[i] = r;
        g_cursor[i] = r;
    }
    if (i == 0) g_rowptr[N] = g_bsum[255];
}

// 4 edges/thread, int4-vectorized loads, 4 independent atomic chains (MLP=4)
__global__ void reorder_edges(const int* __restrict__ src,
                              const int* __restrict__ dst, int E) {
    int tid = blockIdx.x * blockDim.x + threadIdx.x;
    int e0 = tid * 4;
    if (e0 >= E) return;
    if (e0 + 4 <= E) {
        int4 s4 = *(const int4*)(src + e0);
        int4 d4 = *(const int4*)(dst + e0);
        int p0 = atomicAdd(&g_cursor[d4.x], 1);
        int p1 = atomicAdd(&g_cursor[d4.y], 1);
        int p2 = atomicAdd(&g_cursor[d4.z], 1);
        int p3 = atomicAdd(&g_cursor[d4.w], 1);
        g_esrc[p0] = s4.x; g_esrc[p1] = s4.y;
        g_esrc[p2] = s4.z; g_esrc[p3] = s4.w;
    } else {
        for (int e = e0; e < E; e++) {
            int pos = atomicAdd(&g_cursor[dst[e]], 1);
            g_esrc[pos] = src[e];
        }
    }
}

// ---------------- helpers ---------------------------------------------------
__device__ __forceinline__ uint32_t smem_u32(const void* p) {
    uint32_t a;
    asm("{ .reg .u64 t; cvta.to.shared.u64 t, %1; cvt.u32.u64 %0, t; }"
        : "=r"(a) : "l"(p));
    return a;
}

#define LDSM_X4(r0, r1, r2, r3, a) \
    asm volatile("ldmatrix.sync.aligned.m8n8.x4.shared.b16 {%0,%1,%2,%3}, [%4];" \
        : "=r"(r0), "=r"(r1), "=r"(r2), "=r"(r3) : "r"(a))

#define MMA16816(d, a, b0, b1) \
    asm volatile("mma.sync.aligned.m16n8k16.row.col.f32.bf16.bf16.f32 " \
        "{%0,%1,%2,%3}, {%4,%5,%6,%7}, {%8,%9}, {%0,%1,%2,%3};" \
        : "+f"((d)[0]), "+f"((d)[1]), "+f"((d)[2]), "+f"((d)[3]) \
        : "r"((a)[0]), "r"((a)[1]), "r"((a)[2]), "r"((a)[3]), \
          "r"(b0), "r"(b1))

// ---------------- tensor-core (mma.sync) fused GEMM -------------------------
// Grid (782, 2). y=0: feat@W -> g_transformed (fp16); y=1: feat@LW+bias -> out
// bf16 hi/lo 3-term (AhBh + AlBh + AhBl), fp32 accum. PAD=136 -> no conflicts.
#define PAD 136
#define SM_AH 0
#define SM_AL (SM_AH + 64 * PAD * 2)
#define SM_BH (SM_AL + 64 * PAD * 2)
#define SM_BL (SM_BH + 128 * PAD * 2)
#define SM_TOT (SM_BL + 128 * PAD * 2)          // 104448

__global__ __launch_bounds__(256, 2)
void gemm_mma(const float* __restrict__ feat,
              const float* __restrict__ bias,
              float* __restrict__ out, int N) {
    extern __shared__ char smem[];
    const uint32_t sb = smem_u32(smem);
    const int t = threadIdx.x;
    const int w = t >> 5, l = t & 31;
    const int row0 = blockIdx.x * 64;
    const int half = blockIdx.y;

#pragma unroll
    for (int i = 0; i < 8; i++) {
        int idx = t + (i << 8);
        int row = idx >> 5, kq = idx & 31;
        int grow = row0 + row;
        float4 v = make_float4(0.f, 0.f, 0.f, 0.f);
        if (grow < N) v = ((const float4*)feat)[(size_t)grow * 32 + kq];

        __nv_bfloat16 hx = __float2bfloat16(v.x), hy = __float2bfloat16(v.y);
        __nv_bfloat16 hz = __float2bfloat16(v.z), hw = __float2bfloat16(v.w);
        __nv_bfloat162 h01 = __halves2bfloat162(hx, hy);
        __nv_bfloat162 h23 = __halves2bfloat162(hz, hw);
        __nv_bfloat162 l01 = __halves2bfloat162(
            __float2bfloat16(v.x - __bfloat162float(hx)),
            __float2bfloat16(v.y - __bfloat162float(hy)));
        __nv_bfloat162 l23 = __halves2bfloat162(
            __float2bfloat16(v.z - __bfloat162float(hz)),
            __float2bfloat16(v.w - __bfloat162float(hw)));

        int off = row * (PAD * 2) + kq * 8;
        *(__nv_bfloat162*)(smem + SM_AH + off)     = h01;
        *(__nv_bfloat162*)(smem + SM_AH + off + 4) = h23;
        *(__nv_bfloat162*)(smem + SM_AL + off)     = l01;
        *(__nv_bfloat162*)(smem + SM_AL + off + 4) = l23;
    }
    {
        const uint4* srcH = (const uint4*)(half ? g_BhL : g_BhW);
        const uint4* srcL = (const uint4*)(half ? g_BlL : g_BlW);
#pragma unroll
        for (int i = 0; i < 8; i++) {
            int idx = t + (i << 8);
            int n = idx >> 4, kq = idx & 15;
            int off = n * (PAD * 2) + kq * 16;
            *(uint4*)(smem + SM_BH + off) = srcH[idx];
            *(uint4*)(smem + SM_BL + off) = srcL[idx];
        }
    }
    __syncthreads();

    const int mbase = (w >> 2) * 32;
    const int nbase = (w & 3) * 32;
    const uint32_t aRow = (uint32_t)(mbase + (l & 15)) * (PAD * 2) + (l >> 4) * 16;
    const uint32_t bRow = (uint32_t)(nbase + ((l >> 4) << 3) + (l & 7)) * (PAD * 2)
                        + (((l >> 3) & 1) << 4);

    float acc[2][4][4];
#pragma unroll
    for (int mt = 0; mt < 2; mt++)
#pragma unroll
        for (int nt = 0; nt < 4; nt++)
#pragma unroll
            for (int q = 0; q < 4; q++) acc[mt][nt][q] = 0.f;

#pragma unroll
    for (int ks = 0; ks < 8; ks++) {
        const uint32_t kOff = (uint32_t)ks * 32;
        uint32_t ah[2][4], al[2][4], bh[2][4], bl[2][4];
#pragma unroll
        for (int mt = 0; mt < 2; mt++) {
            uint32_t a0 = sb + aRow + (uint32_t)mt * 16 * (PAD * 2) + kOff;
            LDSM_X4(ah[mt][0], ah[mt][1], ah[mt][2], ah[mt][3], a0 + SM_AH);
            LDSM_X4(al[mt][0], al[mt][1], al[mt][2], al[mt][3], a0 + SM_AL);
        }
#pragma unroll
        for (int np = 0; np < 2; np++) {
            uint32_t b0 = sb + bRow + (uint32_t)np * 16 * (PAD * 2) + kOff;
            LDSM_X4(bh[np][0], bh[np][1], bh[np][2], bh[np][3], b0 + SM_BH);
            LDSM_X4(bl[np][0], bl[np][1], bl[np][2], bl[np][3], b0 + SM_BL);
        }
#pragma unroll
        for (int mt = 0; mt < 2; mt++)
#pragma unroll
            for (int np = 0; np < 2; np++)
#pragma unroll
                for (int s = 0; s < 2; s++) {
                    int nt = np * 2 + s;
                    MMA16816(acc[mt][nt], ah[mt], bh[np][2 * s], bh[np][2 * s + 1]);
                    MMA16816(acc[mt][nt], al[mt], bh[np][2 * s], bh[np][2 * s + 1]);
                    MMA16816(acc[mt][nt], ah[mt], bl[np][2 * s], bl[np][2 * s + 1]);
                }
    }

#pragma unroll
    for (int mt = 0; mt < 2; mt++) {
        int r0 = row0 + mbase + mt * 16 + (l >> 2);
#pragma unroll
        for (int nt = 0; nt < 4; nt++) {
            int col = nbase + nt * 8 + (l & 3) * 2;
            if (half) {
                float bx = bias[col], by = bias[col + 1];
                if (r0 < N)
                    *(float2*)&out[(size_t)r0 * D + col] =
                        make_float2(acc[mt][nt][0] + bx, acc[mt][nt][1] + by);
                if (r0 + 8 < N)
                    *(float2*)&out[(size_t)(r0 + 8) * D + col] =
                        make_float2(acc[mt][nt][2] + bx, acc[mt][nt][3] + by);
            } else {
                if (r0 < N)
                    *(__half2*)&g_transformed[(size_t)r0 * D + col] =
                        __floats2half2_rn(acc[mt][nt][0], acc[mt][nt][1]);
                if (r0 + 8 < N)
                    *(__half2*)&g_transformed[(size_t)(r0 + 8) * D + col] =
                        __floats2half2_rn(acc[mt][nt][2], acc[mt][nt][3]);
            }
        }
    }
}

// ---------------- gather-aggregate: warp per node, NO atomics ---------------
__global__ void aggregate(float* __restrict__ out, int N) {
    const int v = (int)((blockIdx.x * blockDim.x + threadIdx.x) >> 5);
    const int lane = threadIdx.x & 31;
    if (v >= N) return;

    const int beg = g_rowptr[v];
    const int end = g_rowptr[v + 1];
    float4 acc = make_float4(0.f, 0.f, 0.f, 0.f);

    int j = beg;
    for (; j + 4 <= end; j += 4) {
        int s0 = __ldg(g_esrc + j);
        int s1 = __ldg(g_esrc + j + 1);
        int s2 = __ldg(g_esrc + j + 2);
        int s3 = __ldg(g_esrc + j + 3);
        uint2 r0 = *(const uint2*)(g_transformed + (size_t)s0 * D + lane * 4);
        uint2 r1 = *(const uint2*)(g_transformed + (size_t)s1 * D + lane * 4);
        uint2 r2 = *(const uint2*)(g_transformed + (size_t)s2 * D + lane * 4);
        uint2 r3 = *(const uint2*)(g_transformed + (size_t)s3 * D + lane * 4);
        float2 a0 = __half22float2(*(__half2*)&r0.x), b0 = __half22float2(*(__half2*)&r0.y);
        float2 a1 = __half22float2(*(__half2*)&r1.x), b1 = __half22float2(*(__half2*)&r1.y);
        float2 a2 = __half22float2(*(__half2*)&r2.x), b2 = __half22float2(*(__half2*)&r2.y);
        float2 a3 = __half22float2(*(__half2*)&r3.x), b3 = __half22float2(*(__half2*)&r3.y);
        acc.x += (a0.x + a1.x) + (a2.x + a3.x);
        acc.y += (a0.y + a1.y) + (a2.y + a3.y);
        acc.z += (b0.x + b1.x) + (b2.x + b3.x);
        acc.w += (b0.y + b1.y) + (b2.y + b3.y);
    }
    for (; j < end; j++) {
        int s = __ldg(g_esrc + j);
        uint2 r = *(const uint2*)(g_transformed + (size_t)s * D + lane * 4);
        float2 a = __half22float2(*(__half2*)&r.x);
        float2 b = __half22float2(*(__half2*)&r.y);
        acc.x += a.x; acc.y += a.y; acc.z += b.x; acc.w += b.y;
    }

    float4* op = (float4*)(out + (size_t)v * D + lane * 4);
    float4 o = *op;
    o.x += acc.x; o.y += acc.y; o.z += acc.z; o.w += acc.w;
    *op = o;
}

extern "C" void kernel_launch(void* const* d_in, const int* in_sizes, int n_in,
                              void* d_out, int out_size) {
    const float* feat = (const float*)d_in[0];   // [N, 128]
    const float* W    = (const float*)d_in[1];   // [128, 128]
    const float* bias = (const float*)d_in[2];   // [128]
    const float* LW   = (const float*)d_in[3];   // [128, 128]
    const int*   src  = (const int*)d_in[4];     // [E]
    const int*   dst  = (const int*)d_in[5];     // [E]
    float* out = (float*)d_out;                  // [N, 128]

    const int N = in_sizes[0] / D;
    const int E = in_sizes[4];
    const int nb = (N + 255) / 256;              // scan blocks (<=255)

    cudaFuncSetAttribute(gemm_mma, cudaFuncAttributeMaxDynamicSharedMemorySize,
                         SM_TOT);

    // CSR build (dst-bucketed edge list)
    prep_B<<<32, 256>>>(W, LW);
    zero_deg<<<nb, 256>>>(N);
    hist_dst<<<1024, 256>>>(dst, E);
    scan_p1<<<nb, 256>>>(N);
    scan_p2<<<1, 256>>>(nb);
    scan_p3<<<nb, 256>>>(N);
    reorder_edges<<<(E / 4 + 255) / 256 + 1, 256>>>(src, dst, E);

    // T = feat@W (fp16) ; out = feat@LW + bias
    dim3 grid((N + 63) / 64, 2);
    gemm_mma<<<grid, 256, SM_TOT>>>(feat, bias, out, N);

    // out[v] += sum of T rows (no atomics)
    aggregate<<<(N * 32 + 255) / 256, 256>>>(out, N);
}

// round 16
// speedup vs baseline: 1.8668x; 1.0607x over previous
#include <cuda_runtime.h>
#include <cuda_bf16.h>
#include <cuda_fp16.h>
#include <cstdint>

#define NODES_MAX 50000
#define EDGES_MAX 800000
#define D 128

typedef unsigned long long ull;

// ---------------- scratch (__device__ globals: allocation-free rule) --------
__device__ __half g_transformed[(size_t)NODES_MAX * D];   // T = feat@W, 12.8 MB
__device__ __nv_bfloat16 g_BhW[128 * 128];
__device__ __nv_bfloat16 g_BlW[128 * 128];
__device__ __nv_bfloat16 g_BhL[128 * 128];
__device__ __nv_bfloat16 g_BlL[128 * 128];
__device__ int g_deg[NODES_MAX];
__device__ int g_rowptr[NODES_MAX + 1];
__device__ int g_cursor[NODES_MAX];
__device__ int g_esrc[EDGES_MAX];          // src ids bucketed by dst
__device__ int g_bsum[256];                // per-block sums for the scan

// ---------------- prep: [W|LW]^T -> bf16 hi/lo (tiled smem transpose) -------
__global__ void prep_B(const float* __restrict__ W, const float* __restrict__ LW) {
    __shared__ float tile[32][33];
    const int mat = blockIdx.x >> 4;
    const int ti = blockIdx.x & 15;
    const int tr = (ti >> 2) * 32;   // k block
    const int tc = (ti & 3) * 32;    // n block
    const float* M = mat ? LW : W;
    __nv_bfloat16* Bh = mat ? g_BhL : g_BhW;
    __nv_bfloat16* Bl = mat ? g_BlL : g_BlW;
    const int t = threadIdx.x;
    const int c = t & 31, r0 = t >> 5;
#pragma unroll
    for (int i = 0; i < 4; i++) {
        int r = r0 + i * 8;
        tile[r][c] = M[(tr + r) * 128 + tc + c];   // coalesced
    }
    __syncthreads();
#pragma unroll
    for (int i = 0; i < 4; i++) {
        int r = r0 + i * 8;
        float w = tile[c][r];                       // conflict-free (pad 33)
        __nv_bfloat16 hi = __float2bfloat16(w);
        __nv_bfloat16 lo = __float2bfloat16(w - __bfloat162float(hi));
        Bh[(tc + r) * 128 + tr + c] = hi;           // coalesced (c = k)
        Bl[(tc + r) * 128 + tr + c] = lo;
    }
}

// ---------------- CSR build --------------------------------------------------
__global__ void zero_deg(int N) {
    int i = blockIdx.x * blockDim.x + threadIdx.x;
    if (i < N) g_deg[i] = 0;
}

__global__ void hist_dst(const int* __restrict__ dst, int E) {
    int i = blockIdx.x * blockDim.x + threadIdx.x;
    int stride = gridDim.x * blockDim.x;
    for (; i < E; i += stride) atomicAdd(&g_deg[dst[i]], 1);
}

// --- multi-block exclusive scan of g_deg (3 phases, all parallel) -----------
__global__ void scan_p1(int N) {
    __shared__ int sh[256];
    const int t = threadIdx.x;
    const int i = blockIdx.x * 256 + t;
    int v = (i < N) ? g_deg[i] : 0;
    sh[t] = v;
    __syncthreads();
#pragma unroll
    for (int off = 1; off < 256; off <<= 1) {
        int x = sh[t];
        int add = (t >= off) ? sh[t - off] : 0;
        __syncthreads();
        sh[t] = x + add;
        __syncthreads();
    }
    if (i < N) g_rowptr[i] = sh[t] - v;        // local exclusive prefix
    if (t == 255) g_bsum[blockIdx.x] = sh[255];
}

__global__ void scan_p2(int nb) {
    __shared__ int sh[256];
    const int t = threadIdx.x;
    int v = (t < nb) ? g_bsum[t] : 0;
    sh[t] = v;
    __syncthreads();
#pragma unroll
    for (int off = 1; off < 256; off <<= 1) {
        int x = sh[t];
        int add = (t >= off) ? sh[t - off] : 0;
        __syncthreads();
        sh[t] = x + add;
        __syncthreads();
    }
    if (t < nb) g_bsum[t] = sh[t] - v;         // exclusive block offsets
    if (t == 0) g_bsum[255] = sh[nb - 1];      // grand total (nb < 255)
}

__global__ void scan_p3(int N) {
    const int i = blockIdx.x * 256 + threadIdx.x;
    if (i < N) {
        int r = g_rowptr[i] + g_bsum[blockIdx.x];
        g_rowptr[i] = r;
        g_cursor[i] = r;
    }
    if (i == 0) g_rowptr[N] = g_bsum[255];
}

// 4 edges/thread, int4-vectorized loads, 4 independent atomic chains (MLP=4)
__global__ void reorder_edges(const int* __restrict__ src,
                              const int* __restrict__ dst, int E) {
    int tid = blockIdx.x * blockDim.x + threadIdx.x;
    int e0 = tid * 4;
    if (e0 >= E) return;
    if (e0 + 4 <= E) {
        int4 s4 = *(const int4*)(src + e0);
        int4 d4 = *(const int4*)(dst + e0);
        int p0 = atomicAdd(&g_cursor[d4.x], 1);
        int p1 = atomicAdd(&g_cursor[d4.y], 1);
        int p2 = atomicAdd(&g_cursor[d4.z], 1);
        int p3 = atomicAdd(&g_cursor[d4.w], 1);
        g_esrc[p0] = s4.x; g_esrc[p1] = s4.y;
        g_esrc[p2] = s4.z; g_esrc[p3] = s4.w;
    } else {
        for (int e = e0; e < E; e++) {
            int pos = atomicAdd(&g_cursor[dst[e]], 1);
            g_esrc[pos] = src[e];
        }
    }
}

// ---------------- helpers ---------------------------------------------------
__device__ __forceinline__ uint32_t smem_u32(const void* p) {
    uint32_t a;
    asm("{ .reg .u64 t; cvta.to.shared.u64 t, %1; cvt.u32.u64 %0, t; }"
        : "=r"(a) : "l"(p));
    return a;
}

#define LDSM_X4(r0, r1, r2, r3, a) \
    asm volatile("ldmatrix.sync.aligned.m8n8.x4.shared.b16 {%0,%1,%2,%3}, [%4];" \
        : "=r"(r0), "=r"(r1), "=r"(r2), "=r"(r3) : "r"(a))

#define MMA16816(d, a, b0, b1) \
    asm volatile("mma.sync.aligned.m16n8k16.row.col.f32.bf16.bf16.f32 " \
        "{%0,%1,%2,%3}, {%4,%5,%6,%7}, {%8,%9}, {%0,%1,%2,%3};" \
        : "+f"((d)[0]), "+f"((d)[1]), "+f"((d)[2]), "+f"((d)[3]) \
        : "r"((a)[0]), "r"((a)[1]), "r"((a)[2]), "r"((a)[3]), \
          "r"(b0), "r"(b1))

// ---------------- tensor-core (mma.sync) fused GEMM -------------------------
// Grid (782, 2). y=0: feat@W -> g_transformed (fp16); y=1: feat@LW+bias -> out
// bf16 hi/lo 3-term (AhBh + AlBh + AhBl), fp32 accum. PAD=136 -> no conflicts.
#define PAD 136
#define SM_AH 0
#define SM_AL (SM_AH + 64 * PAD * 2)
#define SM_BH (SM_AL + 64 * PAD * 2)
#define SM_BL (SM_BH + 128 * PAD * 2)
#define SM_TOT (SM_BL + 128 * PAD * 2)          // 104448

__global__ __launch_bounds__(256, 2)
void gemm_mma(const float* __restrict__ feat,
              const float* __restrict__ bias,
              float* __restrict__ out, int N) {
    extern __shared__ char smem[];
    const uint32_t sb = smem_u32(smem);
    const int t = threadIdx.x;
    const int w = t >> 5, l = t & 31;
    const int row0 = blockIdx.x * 64;
    const int half = blockIdx.y;

#pragma unroll
    for (int i = 0; i < 8; i++) {
        int idx = t + (i << 8);
        int row = idx >> 5, kq = idx & 31;
        int grow = row0 + row;
        float4 v = make_float4(0.f, 0.f, 0.f, 0.f);
        if (grow < N) v = ((const float4*)feat)[(size_t)grow * 32 + kq];

        __nv_bfloat16 hx = __float2bfloat16(v.x), hy = __float2bfloat16(v.y);
        __nv_bfloat16 hz = __float2bfloat16(v.z), hw = __float2bfloat16(v.w);
        __nv_bfloat162 h01 = __halves2bfloat162(hx, hy);
        __nv_bfloat162 h23 = __halves2bfloat162(hz, hw);
        __nv_bfloat162 l01 = __halves2bfloat162(
            __float2bfloat16(v.x - __bfloat162float(hx)),
            __float2bfloat16(v.y - __bfloat162float(hy)));
        __nv_bfloat162 l23 = __halves2bfloat162(
            __float2bfloat16(v.z - __bfloat162float(hz)),
            __float2bfloat16(v.w - __bfloat162float(hw)));

        int off = row * (PAD * 2) + kq * 8;
        *(__nv_bfloat162*)(smem + SM_AH + off)     = h01;
        *(__nv_bfloat162*)(smem + SM_AH + off + 4) = h23;
        *(__nv_bfloat162*)(smem + SM_AL + off)     = l01;
        *(__nv_bfloat162*)(smem + SM_AL + off + 4) = l23;
    }
    {
        const uint4* srcH = (const uint4*)(half ? g_BhL : g_BhW);
        const uint4* srcL = (const uint4*)(half ? g_BlL : g_BlW);
#pragma unroll
        for (int i = 0; i < 8; i++) {
            int idx = t + (i << 8);
            int n = idx >> 4, kq = idx & 15;
            int off = n * (PAD * 2) + kq * 16;
            *(uint4*)(smem + SM_BH + off) = srcH[idx];
            *(uint4*)(smem + SM_BL + off) = srcL[idx];
        }
    }
    __syncthreads();

    const int mbase = (w >> 2) * 32;
    const int nbase = (w & 3) * 32;
    const uint32_t aRow = (uint32_t)(mbase + (l & 15)) * (PAD * 2) + (l >> 4) * 16;
    const uint32_t bRow = (uint32_t)(nbase + ((l >> 4) << 3) + (l & 7)) * (PAD * 2)
                        + (((l >> 3) & 1) << 4);

    float acc[2][4][4];
#pragma unroll
    for (int mt = 0; mt < 2; mt++)
#pragma unroll
        for (int nt = 0; nt < 4; nt++)
#pragma unroll
            for (int q = 0; q < 4; q++) acc[mt][nt][q] = 0.f;

#pragma unroll
    for (int ks = 0; ks < 8; ks++) {
        const uint32_t kOff = (uint32_t)ks * 32;
        uint32_t ah[2][4], al[2][4], bh[2][4], bl[2][4];
#pragma unroll
        for (int mt = 0; mt < 2; mt++) {
            uint32_t a0 = sb + aRow + (uint32_t)mt * 16 * (PAD * 2) + kOff;
            LDSM_X4(ah[mt][0], ah[mt][1], ah[mt][2], ah[mt][3], a0 + SM_AH);
            LDSM_X4(al[mt][0], al[mt][1], al[mt][2], al[mt][3], a0 + SM_AL);
        }
#pragma unroll
        for (int np = 0; np < 2; np++) {
            uint32_t b0 = sb + bRow + (uint32_t)np * 16 * (PAD * 2) + kOff;
            LDSM_X4(bh[np][0], bh[np][1], bh[np][2], bh[np][3], b0 + SM_BH);
            LDSM_X4(bl[np][0], bl[np][1], bl[np][2], bl[np][3], b0 + SM_BL);
        }
#pragma unroll
        for (int mt = 0; mt < 2; mt++)
#pragma unroll
            for (int np = 0; np < 2; np++)
#pragma unroll
                for (int s = 0; s < 2; s++) {
                    int nt = np * 2 + s;
                    MMA16816(acc[mt][nt], ah[mt], bh[np][2 * s], bh[np][2 * s + 1]);
                    MMA16816(acc[mt][nt], al[mt], bh[np][2 * s], bh[np][2 * s + 1]);
                    MMA16816(acc[mt][nt], ah[mt], bl[np][2 * s], bl[np][2 * s + 1]);
                }
    }

#pragma unroll
    for (int mt = 0; mt < 2; mt++) {
        int r0 = row0 + mbase + mt * 16 + (l >> 2);
#pragma unroll
        for (int nt = 0; nt < 4; nt++) {
            int col = nbase + nt * 8 + (l & 3) * 2;
            if (half) {
                float bx = bias[col], by = bias[col + 1];
                if (r0 < N)
                    *(float2*)&out[(size_t)r0 * D + col] =
                        make_float2(acc[mt][nt][0] + bx, acc[mt][nt][1] + by);
                if (r0 + 8 < N)
                    *(float2*)&out[(size_t)(r0 + 8) * D + col] =
                        make_float2(acc[mt][nt][2] + bx, acc[mt][nt][3] + by);
            } else {
                if (r0 < N)
                    *(__half2*)&g_transformed[(size_t)r0 * D + col] =
                        __floats2half2_rn(acc[mt][nt][0], acc[mt][nt][1]);
                if (r0 + 8 < N)
                    *(__half2*)&g_transformed[(size_t)(r0 + 8) * D + col] =
                        __floats2half2_rn(acc[mt][nt][2], acc[mt][nt][3]);
            }
        }
    }
}

// ---------------- gather-aggregate: warp per node, NO atomics ---------------
__global__ void aggregate(float* __restrict__ out, int N) {
    const int v = (int)((blockIdx.x * blockDim.x + threadIdx.x) >> 5);
    const int lane = threadIdx.x & 31;
    if (v >= N) return;

    const int beg = g_rowptr[v];
    const int end = g_rowptr[v + 1];
    float4 acc = make_float4(0.f, 0.f, 0.f, 0.f);

    int j = beg;
    for (; j + 4 <= end; j += 4) {
        int s0 = __ldg(g_esrc + j);
        int s1 = __ldg(g_esrc + j + 1);
        int s2 = __ldg(g_esrc + j + 2);
        int s3 = __ldg(g_esrc + j + 3);
        uint2 r0 = *(const uint2*)(g_transformed + (size_t)s0 * D + lane * 4);
        uint2 r1 = *(const uint2*)(g_transformed + (size_t)s1 * D + lane * 4);
        uint2 r2 = *(const uint2*)(g_transformed + (size_t)s2 * D + lane * 4);
        uint2 r3 = *(const uint2*)(g_transformed + (size_t)s3 * D + lane * 4);
        float2 a0 = __half22float2(*(__half2*)&r0.x), b0 = __half22float2(*(__half2*)&r0.y);
        float2 a1 = __half22float2(*(__half2*)&r1.x), b1 = __half22float2(*(__half2*)&r1.y);
        float2 a2 = __half22float2(*(__half2*)&r2.x), b2 = __half22float2(*(__half2*)&r2.y);
        float2 a3 = __half22float2(*(__half2*)&r3.x), b3 = __half22float2(*(__half2*)&r3.y);
        acc.x += (a0.x + a1.x) + (a2.x + a3.x);
        acc.y += (a0.y + a1.y) + (a2.y + a3.y);
        acc.z += (b0.x + b1.x) + (b2.x + b3.x);
        acc.w += (b0.y + b1.y) + (b2.y + b3.y);
    }
    for (; j < end; j++) {
        int s = __ldg(g_esrc + j);
        uint2 r = *(const uint2*)(g_transformed + (size_t)s * D + lane * 4);
        float2 a = __half22float2(*(__half2*)&r.x);
        float2 b = __half22float2(*(__half2*)&r.y);
        acc.x += a.x; acc.y += a.y; acc.z += b.x; acc.w += b.y;
    }

    float4* op = (float4*)(out + (size_t)v * D + lane * 4);
    float4 o = *op;
    o.x += acc.x; o.y += acc.y; o.z += acc.z; o.w += acc.w;
    *op = o;
}

extern "C" void kernel_launch(void* const* d_in, const int* in_sizes, int n_in,
                              void* d_out, int out_size) {
    const float* feat = (const float*)d_in[0];   // [N, 128]
    const float* W    = (const float*)d_in[1];   // [128, 128]
    const float* bias = (const float*)d_in[2];   // [128]
    const float* LW   = (const float*)d_in[3];   // [128, 128]
    const int*   src  = (const int*)d_in[4];     // [E]
    const int*   dst  = (const int*)d_in[5];     // [E]
    float* out = (float*)d_out;                  // [N, 128]

    const int N = in_sizes[0] / D;
    const int E = in_sizes[4];
    const int nb = (N + 255) / 256;              // scan blocks (<=255)

    cudaFuncSetAttribute(gemm_mma, cudaFuncAttributeMaxDynamicSharedMemorySize,
                         SM_TOT);

    // Fork a side stream for the (independent) CSR build so the captured
    // graph runs it concurrently with the GEMM path. Stream/event creation is
    // host-side only (no device memory). kernel_launch runs only a handful of
    // times (correctness + capture), so not destroying them is leak-safe and
    // avoids invalidating an in-progress capture via cudaStreamDestroy.
    cudaStream_t s2;
    cudaStreamCreateWithFlags(&s2, cudaStreamNonBlocking);
    cudaEvent_t evFork, evJoin;
    cudaEventCreateWithFlags(&evFork, cudaEventDisableTiming);
    cudaEventCreateWithFlags(&evJoin, cudaEventDisableTiming);

    cudaEventRecord(evFork, 0);
    cudaStreamWaitEvent(s2, evFork, 0);

    // --- branch A (side stream): CSR build ---------------------------------
    zero_deg<<<nb, 256, 0, s2>>>(N);
    hist_dst<<<1024, 256, 0, s2>>>(dst, E);
    scan_p1<<<nb, 256, 0, s2>>>(N);
    scan_p2<<<1, 256, 0, s2>>>(nb);
    scan_p3<<<nb, 256, 0, s2>>>(N);
    reorder_edges<<<(E / 4 + 255) / 256 + 1, 256, 0, s2>>>(src, dst, E);
    cudaEventRecord(evJoin, s2);

    // --- branch B (main stream): weight prep + GEMM ------------------------
    prep_B<<<32, 256>>>(W, LW);
    dim3 grid((N + 63) / 64, 2);
    gemm_mma<<<grid, 256, SM_TOT>>>(feat, bias, out, N);

    // --- join, then aggregate (needs T from B and CSR from A) --------------
    cudaStreamWaitEvent(0, evJoin, 0);
    aggregate<<<(N * 32 + 255) / 256, 256>>>(out, N);
}